// round 2
// baseline (speedup 1.0000x reference)
#include <cuda_runtime.h>
#include <math.h>

// Problem constants
#define B_ 256
#define N_ 256
#define C_ 768
#define A_ 10
#define H_ 8
#define E_ 4
#define D_ 96
#define SCALE_ 0.10206207261596575f   // 96^-0.5

// ---------------- device scratch (no allocations allowed) ----------------
__device__ float g_qb[B_*C_];                 // q projection [B,C]
__device__ float g_qhat[B_*H_*C_];            // Wk_h^T q_h   [B,H,C]
__device__ float g_xbar[B_*H_*C_];            // softmax-weighted patch sum [B,H,C]
__device__ float g_o[B_*C_];                  // attention output pre-Wo [B,C]
__device__ float g_uP[(B_+A_)*C_];            // rows 0..255: u[b]=moe_in+visual_cls ; rows 256..265: prompt[a]
__device__ float g_Yw[(B_+A_)*E_*C_];         // expert outputs: row i, col e*C+o
__device__ float g_gate[(B_+A_)*E_];          // gate dots per row
__device__ float g_dr[(B_+A_)];               // router fc1 dots per row

// ---------------- generic fp32 GEMM: Y = X * W(^T) (+bias)(+extra) -------
// TRANSB=true : W is [N,K] row-major  (torch Linear weight)
// TRANSB=false: W is [K,N] row-major
template<bool TRANSB, bool HAS_BIAS, bool HAS_EXTRA>
__global__ void __launch_bounds__(256) gemm_k(
    int M, int N, int K,
    const float* __restrict__ X, int lda, int sx,
    const float* __restrict__ W, int ldw, int sw,
    float* __restrict__ Y, int ldy, int sy,
    const float* __restrict__ bias, int sb,
    const float* __restrict__ extra, int lde)
{
    constexpr int BM = 64, BN = 64, BK = 8;
    int z = blockIdx.z;
    X += (size_t)z * sx;
    W += (size_t)z * sw;
    Y += (size_t)z * sy;
    if (HAS_BIAS) bias += (size_t)z * sb;

    __shared__ __align__(16) float As[BK][BM + 4];
    __shared__ __align__(16) float Bs[BK][BN + 4];

    int tid = threadIdx.x;
    int m0 = blockIdx.y * BM, n0 = blockIdx.x * BN;
    int tx = tid & 15, ty = tid >> 4;

    float acc[4][4];
#pragma unroll
    for (int i = 0; i < 4; i++)
#pragma unroll
        for (int j = 0; j < 4; j++) acc[i][j] = 0.f;

    for (int k0 = 0; k0 < K; k0 += BK) {
#pragma unroll
        for (int jj = 0; jj < 2; jj++) {
            int idx = tid + jj * 256;
            int mi = idx >> 3, ki = idx & 7;
            int m = m0 + mi;
            As[ki][mi] = (m < M) ? X[(size_t)m * lda + (k0 + ki)] : 0.f;
        }
#pragma unroll
        for (int jj = 0; jj < 2; jj++) {
            int idx = tid + jj * 256;
            if (TRANSB) {
                int ni = idx >> 3, ki = idx & 7;
                int n = n0 + ni;
                Bs[ki][ni] = (n < N) ? W[(size_t)n * ldw + (k0 + ki)] : 0.f;
            } else {
                int ki = idx >> 6, ni = idx & 63;
                int n = n0 + ni;
                Bs[ki][ni] = (n < N) ? W[(size_t)(k0 + ki) * ldw + n] : 0.f;
            }
        }
        __syncthreads();
#pragma unroll
        for (int kk = 0; kk < BK; kk++) {
            float4 av  = *reinterpret_cast<const float4*>(&As[kk][ty * 4]);
            float4 bv4 = *reinterpret_cast<const float4*>(&Bs[kk][tx * 4]);
            float a[4]  = {av.x, av.y, av.z, av.w};
            float bb[4] = {bv4.x, bv4.y, bv4.z, bv4.w};
#pragma unroll
            for (int i = 0; i < 4; i++)
#pragma unroll
                for (int j = 0; j < 4; j++)
                    acc[i][j] = fmaf(a[i], bb[j], acc[i][j]);
        }
        __syncthreads();
    }

#pragma unroll
    for (int i = 0; i < 4; i++) {
        int m = m0 + ty * 4 + i;
        if (m >= M) continue;
#pragma unroll
        for (int j = 0; j < 4; j++) {
            int n = n0 + tx * 4 + j;
            if (n >= N) continue;
            float v = acc[i][j];
            if (HAS_BIAS)  v += bias[n];
            if (HAS_EXTRA) v += extra[(size_t)m * lde + n];
            Y[(size_t)m * ldy + n] = v;
        }
    }
}

// ---------------- fused 1-query flash attention over visual_patchs -------
// grid = B, block = 256 (8 warps == 8 heads). Single pass over x[b].
// Computes xbar[b,h,:] = sum_n softmax_n(qhat[b,h]·x[b,n]*scale) * x[b,n,:]
__global__ void __launch_bounds__(256) attn_k(
    const float* __restrict__ xg, const float* __restrict__ qhat,
    float* __restrict__ xbar)
{
    int b = blockIdx.x;
    int tid = threadIdx.x, w = tid >> 5, lane = tid & 31;
    __shared__ __align__(16) float qh[H_ * C_];   // 24 KB
    __shared__ __align__(16) float xs[8][C_];     // 24 KB staged patch rows

    const float* xb = xg + (size_t)b * N_ * C_;
    {
        const float4* src = (const float4*)(qhat + (size_t)b * H_ * C_);
        float4* dstq = (float4*)qh;
#pragma unroll
        for (int i = 0; i < 6; i++) dstq[tid + i * 256] = src[tid + i * 256];
    }
    __syncthreads();

    const float* qw = qh + w * C_;
    float m = -INFINITY, s = 0.f;
    float acc[24];
#pragma unroll
    for (int j = 0; j < 24; j++) acc[j] = 0.f;

    for (int nb = 0; nb < N_; nb += 8) {
        __syncthreads();
        const float4* src = (const float4*)(xb + (size_t)nb * C_);
        float4* dst = (float4*)(&xs[0][0]);
#pragma unroll
        for (int i = 0; i < 6; i++) dst[tid + i * 256] = src[tid + i * 256];
        __syncthreads();
#pragma unroll
        for (int r = 0; r < 8; r++) {
            const float* xr = xs[r];
            float part = 0.f;
#pragma unroll
            for (int j = 0; j < 24; j++)
                part = fmaf(qw[j * 32 + lane], xr[j * 32 + lane], part);
#pragma unroll
            for (int o = 16; o; o >>= 1)
                part += __shfl_xor_sync(0xffffffffu, part, o);
            float l = part * SCALE_;          // uniform across warp
            if (l > m) {                       // uniform branch
                float corr = __expf(m - l);    // 0 on first row (m=-inf)
                s = s * corr + 1.f;
#pragma unroll
                for (int j = 0; j < 24; j++)
                    acc[j] = fmaf(acc[j], corr, xr[j * 32 + lane]);
                m = l;
            } else {
                float p = __expf(l - m);
                s += p;
#pragma unroll
                for (int j = 0; j < 24; j++)
                    acc[j] = fmaf(p, xr[j * 32 + lane], acc[j]);
            }
        }
    }
    float inv = 1.f / s;
    float* outp = xbar + (size_t)b * H_ * C_ + w * C_;
#pragma unroll
    for (int j = 0; j < 24; j++) outp[j * 32 + lane] = acc[j] * inv;
}

// ---------------- prompt rows into uP ------------------------------------
__global__ void copy_prompt_k(const float* __restrict__ prompt, float* __restrict__ uP)
{
    uP[(size_t)(B_ + blockIdx.x) * C_ + threadIdx.x] =
        prompt[(size_t)blockIdx.x * C_ + threadIdx.x];
}

// ---------------- gate + router-fc1 dots for all 266 rows ----------------
__global__ void __launch_bounds__(160) dots_k(
    const float* __restrict__ uP, const float* __restrict__ gate_w,
    const float* __restrict__ r1_w, float* __restrict__ gate_out,
    float* __restrict__ dr_out)
{
    int i = blockIdx.x;
    int w = threadIdx.x >> 5, lane = threadIdx.x & 31;
    const float* u = uP + (size_t)i * C_;
    const float* v = (w < 4) ? (gate_w + w * C_) : r1_w;
    float p = 0.f;
#pragma unroll
    for (int j = 0; j < 24; j++) p = fmaf(u[j * 32 + lane], v[j * 32 + lane], p);
#pragma unroll
    for (int o = 16; o; o >>= 1) p += __shfl_xor_sync(0xffffffffu, p, o);
    if (lane == 0) {
        if (w < 4) gate_out[i * E_ + w] = p;
        else       dr_out[i] = p;
    }
}

// ---------------- final combine per batch row ----------------------------
__global__ void __launch_bounds__(256) finale_k(
    const float* __restrict__ Yw, const float* __restrict__ gate,
    const float* __restrict__ dr, const float* __restrict__ gate_b,
    const float* __restrict__ exp_b, const float* __restrict__ r1_b,
    const float* __restrict__ r2_w, const float* __restrict__ r2_b,
    float* __restrict__ out)
{
    int b = blockIdx.x, tid = threadIdx.x;
    __shared__ float red[256];
    __shared__ float s_mr2, s_mrb;
    __shared__ float s_w[A_][E_];
    __shared__ float s_sc[A_];
    __shared__ float s_c1[E_];
    __shared__ float s_c2[A_][E_];

    // means of r2_w, r2_b over channels
    float sum2 = 0.f, sumb = 0.f;
#pragma unroll
    for (int j = 0; j < 3; j++) {
        sum2 += r2_w[tid + j * 256];
        sumb += r2_b[tid + j * 256];
    }
    red[tid] = sum2; __syncthreads();
    for (int st = 128; st > 0; st >>= 1) { if (tid < st) red[tid] += red[tid + st]; __syncthreads(); }
    if (tid == 0) s_mr2 = red[0] * (1.f / C_);
    __syncthreads();
    red[tid] = sumb; __syncthreads();
    for (int st = 128; st > 0; st >>= 1) { if (tid < st) red[tid] += red[tid + st]; __syncthreads(); }
    if (tid == 0) s_mrb = red[0] * (1.f / C_);
    __syncthreads();

    if (tid < A_) {
        int a = tid;
        float g[E_];
#pragma unroll
        for (int e = 0; e < E_; e++)
            g[e] = gate[b * E_ + e] + gate[(B_ + a) * E_ + e] + gate_b[e];
        // MoE top-3 of 4: drop the min, softmax over the rest
        int mi = 0;
#pragma unroll
        for (int e = 1; e < E_; e++) if (g[e] < g[mi]) mi = e;
        float mx = -INFINITY;
#pragma unroll
        for (int e = 0; e < E_; e++) if (e != mi && g[e] > mx) mx = g[e];
        float ssum = 0.f, we[E_];
#pragma unroll
        for (int e = 0; e < E_; e++) {
            we[e] = (e == mi) ? 0.f : __expf(g[e] - mx);
            ssum += we[e];
        }
        float inv = 1.f / ssum;
#pragma unroll
        for (int e = 0; e < E_; e++) s_w[a][e] = we[e] * inv;
        // router score: gelu_tanh(du+dp+b1) * mean(r2_w) + mean(r2_b)
        float xv = dr[b] + dr[B_ + a] + r1_b[0];
        float hg = 0.5f * xv * (1.f + tanhf(0.7978845608028654f * (xv + 0.044715f * xv * xv * xv)));
        s_sc[a] = hg * s_mr2 + s_mrb;
    }
    __syncthreads();

    if (tid == 0) {
        // top-7 of 10: exclude the 3 smallest scores
        bool excl[A_];
        for (int a = 0; a < A_; a++) excl[a] = false;
        for (int r = 0; r < 3; r++) {
            int mi = -1; float mv = INFINITY;
            for (int a = 0; a < A_; a++)
                if (!excl[a] && s_sc[a] < mv) { mv = s_sc[a]; mi = a; }
            excl[mi] = true;
        }
        float smax = -INFINITY;
        for (int a = 0; a < A_; a++) if (!excl[a] && s_sc[a] > smax) smax = s_sc[a];
        float ssum = 0.f, wt[A_];
        for (int a = 0; a < A_; a++) {
            wt[a] = excl[a] ? 0.f : __expf(s_sc[a] - smax);
            ssum += wt[a];
        }
        float inv = 1.f / ssum;
        for (int e = 0; e < E_; e++) {
            float c1 = 0.f;
            for (int a = 0; a < A_; a++) {
                float c2 = wt[a] * inv * s_w[a][e];
                s_c2[a][e] = c2;
                c1 += c2;
            }
            s_c1[e] = c1;
        }
    }
    __syncthreads();

#pragma unroll
    for (int j = 0; j < 3; j++) {
        int c = tid + j * 256;
        float v = 0.f;
#pragma unroll
        for (int e = 0; e < E_; e++)
            v += s_c1[e] * (Yw[(size_t)b * (E_ * C_) + e * C_ + c] + exp_b[e * C_ + c]);
#pragma unroll
        for (int a = 0; a < A_; a++)
#pragma unroll
            for (int e = 0; e < E_; e++)
                v += s_c2[a][e] * Yw[(size_t)(B_ + a) * (E_ * C_) + e * C_ + c];
        out[(size_t)b * C_ + c] = v;
    }
}

// ---------------- launcher ----------------------------------------------
extern "C" void kernel_launch(void* const* d_in, const int* in_sizes, int n_in,
                              void* d_out, int out_size)
{
    (void)in_sizes; (void)n_in; (void)out_size;
    const float* text   = (const float*)d_in[0];
    const float* vcls   = (const float*)d_in[1];
    const float* x      = (const float*)d_in[2];
    const float* prompt = (const float*)d_in[3];
    const float* Wq = (const float*)d_in[4];
    const float* bq = (const float*)d_in[5];
    const float* Wk = (const float*)d_in[6];
    // d_in[7] = bk : per-(b,h) constant logit shift -> softmax-invariant, unused
    const float* Wv = (const float*)d_in[8];
    const float* bv = (const float*)d_in[9];
    const float* Wo = (const float*)d_in[10];
    const float* bo = (const float*)d_in[11];
    const float* gate_w = (const float*)d_in[12];
    const float* gate_b = (const float*)d_in[13];
    const float* exp_w  = (const float*)d_in[14];
    const float* exp_b  = (const float*)d_in[15];
    const float* r1_w   = (const float*)d_in[16];
    const float* r1_b   = (const float*)d_in[17];
    const float* r2_w   = (const float*)d_in[18];
    const float* r2_b   = (const float*)d_in[19];
    float* out = (float*)d_out;

    void* p;
    cudaGetSymbolAddress(&p, g_qb);   float* qb   = (float*)p;
    cudaGetSymbolAddress(&p, g_qhat); float* qhat = (float*)p;
    cudaGetSymbolAddress(&p, g_xbar); float* xbar = (float*)p;
    cudaGetSymbolAddress(&p, g_o);    float* o    = (float*)p;
    cudaGetSymbolAddress(&p, g_uP);   float* uP   = (float*)p;
    cudaGetSymbolAddress(&p, g_Yw);   float* Yw   = (float*)p;
    cudaGetSymbolAddress(&p, g_gate); float* gate = (float*)p;
    cudaGetSymbolAddress(&p, g_dr);   float* dr   = (float*)p;

    // prompt rows of uP (independent)
    copy_prompt_k<<<A_, C_>>>(prompt, uP);

    // qb[b,:] = text_cls[b] @ Wq^T + bq
    gemm_k<true, true, false><<<dim3(12, 4, 1), 256>>>(
        B_, C_, C_, text, C_, 0, Wq, C_, 0, qb, C_, 0, bq, 0, nullptr, 0);

    // qhat[b,h,c] = sum_d Wk[h*96+d, c] * qb[b, h*96+d]   (batched over h)
    gemm_k<false, false, false><<<dim3(12, 4, H_), 256>>>(
        B_, C_, D_, qb, C_, D_, Wk, C_, D_ * C_, qhat, H_ * C_, C_,
        nullptr, 0, nullptr, 0);

    // flash attention: xbar[b,h,:] (single pass over visual_patchs)
    attn_k<<<B_, 256>>>(x, qhat, xbar);

    // o[b, h*96+d] = Wv_h @ xbar[b,h] + bv_h   (batched over h)
    gemm_k<true, true, false><<<dim3(2, 4, H_), 256>>>(
        B_, D_, C_, xbar, H_ * C_, C_, Wv, C_, D_ * C_, o, C_, D_,
        bv, D_, nullptr, 0);

    // u[b] = o[b] @ Wo^T + bo + visual_cls[b]  -> uP rows 0..255
    gemm_k<true, true, true><<<dim3(12, 4, 1), 256>>>(
        B_, C_, C_, o, C_, 0, Wo, C_, 0, uP, C_, 0, bo, 0, vcls, C_);

    // expert outputs for all 266 rows: Yw[i, e*C+o] = uP[i] @ exp_w[e]^T
    gemm_k<true, false, false><<<dim3(48, 5, 1), 256>>>(
        B_ + A_, E_ * C_, C_, uP, C_, 0, exp_w, C_, 0, Yw, E_ * C_, 0,
        nullptr, 0, nullptr, 0);

    // gate + router-fc1 dots
    dots_k<<<B_ + A_, 160>>>(uP, gate_w, r1_w, gate, dr);

    // scores, top-k, softmax weights, weighted expert combine
    finale_k<<<B_, 256>>>(Yw, gate, dr, gate_b, exp_b, r1_b, r2_w, r2_b, out);
}

// round 3
// speedup vs baseline: 2.2738x; 2.2738x over previous
#include <cuda_runtime.h>
#include <math.h>
#include <stdint.h>

// Problem constants
#define B_ 256
#define N_ 256
#define C_ 768
#define A_ 10
#define H_ 8
#define E_ 4
#define D_ 96
#define SCALE_ 0.10206207261596575f   // 96^-0.5
#define SPLITS_ 4                     // attention N-splits

// ---------------- device scratch (no allocations allowed) ----------------
__device__ float g_qb[B_*C_];                  // q projection [B,C]
__device__ float g_qhat[B_*H_*C_];             // Wk_h^T q_h   [B,H,C]
__device__ float g_xbar[B_*H_*C_];             // softmax-weighted patch sum [B,H,C]
__device__ float g_o[B_*C_];                   // attention output pre-Wo [B,C]
__device__ float g_uP[(B_+A_)*C_];             // rows 0..255: u[b] ; rows 256..265: prompt[a]
__device__ float g_Yw[(B_+A_)*E_*C_];          // expert outputs
__device__ float g_gate[(B_+A_)*E_];
__device__ float g_dr[(B_+A_)];
__device__ float g_split[2*266*3072];          // split-K partials (largest user: expert KS=2)
__device__ float g_pacc[SPLITS_*B_*H_*C_];     // attention partial accumulators (25MB)
__device__ float2 g_pms[SPLITS_*B_*H_];        // attention partial (max, sum)

// ---------------- cp.async helpers ---------------------------------------
__device__ __forceinline__ void cp_async16(void* smem_dst, const void* gmem_src) {
    uint32_t d = (uint32_t)__cvta_generic_to_shared(smem_dst);
    asm volatile("cp.async.cg.shared.global [%0], [%1], 16;\n" :: "r"(d), "l"(gmem_src));
}
#define CP_COMMIT() asm volatile("cp.async.commit_group;\n" ::: "memory")
#define CP_WAIT(n)  asm volatile("cp.async.wait_group %0;\n" :: "n"(n) : "memory")

// ---------------- fp32 GEMM, BK=16, register prefetch, optional split-K ---
// TRANSB=true : W is [N,K] row-major (torch Linear weight). PARTIAL: write
// raw partial tile to P[z][M][N] where z = batch*KS + ks (reduced later).
template<bool TRANSB, bool PARTIAL, bool HAS_BIAS, bool HAS_EXTRA>
__global__ void __launch_bounds__(256) gemm2_k(
    int M, int N, int K, int KS,
    const float* __restrict__ X, int lda, int sx,
    const float* __restrict__ W, int ldw, int sw,
    float* __restrict__ Y, int ldy, int sy,
    const float* __restrict__ bias, int sb,
    const float* __restrict__ extra, int lde)
{
    constexpr int BM = 64, BN = 64, BK = 16;
    int z = blockIdx.z;
    int batch = z / KS, ks = z - batch * KS;
    int Kloc = K / KS, kbase = ks * Kloc;
    X += (size_t)batch * sx;
    W += (size_t)batch * sw;

    __shared__ __align__(16) float As[BK][BM + 4];
    __shared__ __align__(16) float Bs[BK][BN + 4];

    int tid = threadIdx.x;
    int m0 = blockIdx.y * BM, n0 = blockIdx.x * BN;
    int tx = tid & 15, ty = tid >> 4;

    float acc[4][4];
#pragma unroll
    for (int i = 0; i < 4; i++)
#pragma unroll
        for (int j = 0; j < 4; j++) acc[i][j] = 0.f;

    float ra[4], rb[4];

    auto ldg = [&](int kb) {
#pragma unroll
        for (int j = 0; j < 4; j++) {
            int idx = tid + j * 256;
            int mi = idx >> 4, ki = idx & 15;
            int mm = m0 + mi;
            ra[j] = (mm < M) ? X[(size_t)mm * lda + kb + ki] : 0.f;
        }
        if (TRANSB) {
#pragma unroll
            for (int j = 0; j < 4; j++) {
                int idx = tid + j * 256;
                int ni = idx >> 4, ki = idx & 15;
                int nn = n0 + ni;
                rb[j] = (nn < N) ? W[(size_t)nn * ldw + kb + ki] : 0.f;
            }
        } else {
#pragma unroll
            for (int j = 0; j < 4; j++) {
                int idx = tid + j * 256;
                int ki = idx >> 6, ni = idx & 63;
                int nn = n0 + ni;
                rb[j] = (nn < N) ? W[(size_t)(kb + ki) * ldw + nn] : 0.f;
            }
        }
    };
    auto sts = [&]() {
#pragma unroll
        for (int j = 0; j < 4; j++) {
            int idx = tid + j * 256;
            As[idx & 15][idx >> 4] = ra[j];
        }
        if (TRANSB) {
#pragma unroll
            for (int j = 0; j < 4; j++) {
                int idx = tid + j * 256;
                Bs[idx & 15][idx >> 4] = rb[j];
            }
        } else {
#pragma unroll
            for (int j = 0; j < 4; j++) {
                int idx = tid + j * 256;
                Bs[idx >> 6][idx & 63] = rb[j];
            }
        }
    };

    ldg(kbase);
    sts();
    __syncthreads();
    for (int kb = BK;; kb += BK) {
        bool more = kb < Kloc;
        if (more) ldg(kbase + kb);      // overlap next-chunk LDG with FMA below
#pragma unroll
        for (int kk = 0; kk < BK; kk++) {
            float4 av  = *reinterpret_cast<const float4*>(&As[kk][ty * 4]);
            float4 bv4 = *reinterpret_cast<const float4*>(&Bs[kk][tx * 4]);
            float a[4]  = {av.x, av.y, av.z, av.w};
            float bb[4] = {bv4.x, bv4.y, bv4.z, bv4.w};
#pragma unroll
            for (int i = 0; i < 4; i++)
#pragma unroll
                for (int j = 0; j < 4; j++)
                    acc[i][j] = fmaf(a[i], bb[j], acc[i][j]);
        }
        __syncthreads();
        if (!more) break;
        sts();
        __syncthreads();
    }

    if (PARTIAL) {
        float* P = Y + (size_t)z * M * N;
#pragma unroll
        for (int i = 0; i < 4; i++) {
            int m = m0 + ty * 4 + i;
            if (m >= M) continue;
#pragma unroll
            for (int j = 0; j < 4; j++) {
                int n = n0 + tx * 4 + j;
                if (n >= N) continue;
                P[(size_t)m * N + n] = acc[i][j];
            }
        }
    } else {
        Y += (size_t)batch * sy;
#pragma unroll
        for (int i = 0; i < 4; i++) {
            int m = m0 + ty * 4 + i;
            if (m >= M) continue;
#pragma unroll
            for (int j = 0; j < 4; j++) {
                int n = n0 + tx * 4 + j;
                if (n >= N) continue;
                float v = acc[i][j];
                if (HAS_BIAS)  v += bias[(size_t)batch * sb + n];
                if (HAS_EXTRA) v += extra[(size_t)m * lde + n];
                Y[(size_t)m * ldy + n] = v;
            }
        }
    }
}

// ---------------- split-K reduce ------------------------------------------
template<bool HAS_BIAS, bool HAS_EXTRA>
__global__ void __launch_bounds__(256) reduce_k(
    int M, int N, int KS,
    const float* __restrict__ part, float* __restrict__ Y, int ldy, int sy,
    const float* __restrict__ bias, int sb,
    const float* __restrict__ extra, int lde)
{
    int z2 = blockIdx.y;
    int idx = blockIdx.x * 256 + threadIdx.x;
    if (idx >= M * N) return;
    int m = idx / N, n = idx - m * N;
    const float* p = part + (size_t)z2 * KS * M * N;
    float v = 0.f;
    for (int k = 0; k < KS; k++)
        v += p[(size_t)k * M * N + (size_t)m * N + n];
    if (HAS_BIAS)  v += bias[z2 * sb + n];
    if (HAS_EXTRA) v += extra[(size_t)m * lde + n];
    Y[(size_t)z2 * sy + (size_t)m * ldy + n] = v;
}

// ---------------- attention: split-N partial pass with cp.async pipeline --
// grid = (SPLITS_, B). block 256 = 8 warps = 8 heads. Each block handles 64
// patches, 4-row tiles, double-buffered LDGSTS. Emits unnormalized partial
// (m, s, acc) per (split, b, h).
__global__ void __launch_bounds__(256) attn_part_k(
    const float* __restrict__ xg, const float* __restrict__ qhat,
    float* __restrict__ pacc, float2* __restrict__ pms)
{
    int s = blockIdx.x, b = blockIdx.y;
    int tid = threadIdx.x, w = tid >> 5, lane = tid & 31;
    __shared__ __align__(16) float qh[H_ * C_];      // 24 KB
    __shared__ __align__(16) float xs[2][4][C_];     // 24 KB (double-buffered 4-row tiles)

    const float* xb = xg + ((size_t)b * N_ + (size_t)s * 64) * C_;

    auto issue = [&](int t) {
        int buf = t & 1;
        const float* src0 = xb + (size_t)t * 4 * C_;
#pragma unroll
        for (int i = 0; i < 3; i++) {
            int idx = tid + i * 256;          // float4 index 0..767
            int r = idx / 192, c4 = idx - r * 192;
            cp_async16(&xs[buf][r][c4 * 4], src0 + (size_t)r * C_ + c4 * 4);
        }
        CP_COMMIT();
    };

    issue(0);
    {   // stage all 8 heads' qhat rows
        const float4* src = (const float4*)(qhat + (size_t)b * H_ * C_);
        float4* dst = (float4*)qh;
#pragma unroll
        for (int i = 0; i < 6; i++) dst[tid + i * 256] = src[tid + i * 256];
    }

    const float* qw = qh + w * C_;
    float m = -INFINITY, ssum = 0.f;
    float acc[24];
#pragma unroll
    for (int j = 0; j < 24; j++) acc[j] = 0.f;

    for (int t = 0; t < 16; t++) {
        if (t < 15) { issue(t + 1); CP_WAIT(1); }
        else        { CP_WAIT(0); }
        __syncthreads();
        const int buf = t & 1;
#pragma unroll
        for (int r = 0; r < 4; r++) {
            const float* xr = xs[buf][r];
            float part = 0.f;
#pragma unroll
            for (int j = 0; j < 24; j++)
                part = fmaf(qw[j * 32 + lane], xr[j * 32 + lane], part);
#pragma unroll
            for (int o = 16; o; o >>= 1)
                part += __shfl_xor_sync(0xffffffffu, part, o);
            float l = part * SCALE_;           // uniform across warp
            if (l > m) {
                float corr = __expf(m - l);    // 0 on first row
                ssum = ssum * corr + 1.f;
#pragma unroll
                for (int j = 0; j < 24; j++)
                    acc[j] = fmaf(acc[j], corr, xr[j * 32 + lane]);
                m = l;
            } else {
                float p = __expf(l - m);
                ssum += p;
#pragma unroll
                for (int j = 0; j < 24; j++)
                    acc[j] = fmaf(p, xr[j * 32 + lane], acc[j]);
            }
        }
        __syncthreads();
    }

    float* outp = pacc + ((size_t)(s * B_ + b) * H_ + w) * C_;
#pragma unroll
    for (int j = 0; j < 24; j++) outp[j * 32 + lane] = acc[j];
    if (lane == 0) pms[(size_t)(s * B_ + b) * H_ + w] = make_float2(m, ssum);
}

// ---------------- attention: combine partials -----------------------------
__global__ void __launch_bounds__(256) attn_comb_k(
    const float* __restrict__ pacc, const float2* __restrict__ pms,
    float* __restrict__ xbar)
{
    int b = blockIdx.x;
    int tid = threadIdx.x, w = tid >> 5, lane = tid & 31;
    float2 ms[SPLITS_];
    float wf[SPLITS_];
#pragma unroll
    for (int i = 0; i < SPLITS_; i++) ms[i] = pms[(size_t)(i * B_ + b) * H_ + w];
    float M = ms[0].x;
#pragma unroll
    for (int i = 1; i < SPLITS_; i++) M = fmaxf(M, ms[i].x);
    float S = 0.f;
#pragma unroll
    for (int i = 0; i < SPLITS_; i++) { wf[i] = __expf(ms[i].x - M); S += ms[i].y * wf[i]; }
    float inv = 1.f / S;
#pragma unroll
    for (int j = 0; j < 24; j++) {
        float v = 0.f;
#pragma unroll
        for (int i = 0; i < SPLITS_; i++)
            v += pacc[((size_t)(i * B_ + b) * H_ + w) * C_ + j * 32 + lane] * wf[i];
        xbar[((size_t)b * H_ + w) * C_ + j * 32 + lane] = v * inv;
    }
}

// ---------------- prompt rows into uP -------------------------------------
__global__ void copy_prompt_k(const float* __restrict__ prompt, float* __restrict__ uP)
{
    uP[(size_t)(B_ + blockIdx.x) * C_ + threadIdx.x] =
        prompt[(size_t)blockIdx.x * C_ + threadIdx.x];
}

// ---------------- gate + router-fc1 dots ----------------------------------
__global__ void __launch_bounds__(160) dots_k(
    const float* __restrict__ uP, const float* __restrict__ gate_w,
    const float* __restrict__ r1_w, float* __restrict__ gate_out,
    float* __restrict__ dr_out)
{
    int i = blockIdx.x;
    int w = threadIdx.x >> 5, lane = threadIdx.x & 31;
    const float* u = uP + (size_t)i * C_;
    const float* v = (w < 4) ? (gate_w + w * C_) : r1_w;
    float p = 0.f;
#pragma unroll
    for (int j = 0; j < 24; j++) p = fmaf(u[j * 32 + lane], v[j * 32 + lane], p);
#pragma unroll
    for (int o = 16; o; o >>= 1) p += __shfl_xor_sync(0xffffffffu, p, o);
    if (lane == 0) {
        if (w < 4) gate_out[i * E_ + w] = p;
        else       dr_out[i] = p;
    }
}

// ---------------- final combine per batch row -----------------------------
__global__ void __launch_bounds__(256) finale_k(
    const float* __restrict__ Yw, const float* __restrict__ gate,
    const float* __restrict__ dr, const float* __restrict__ gate_b,
    const float* __restrict__ exp_b, const float* __restrict__ r1_b,
    const float* __restrict__ r2_w, const float* __restrict__ r2_b,
    float* __restrict__ out)
{
    int b = blockIdx.x, tid = threadIdx.x;
    __shared__ float red[256];
    __shared__ float s_mr2, s_mrb;
    __shared__ float s_w[A_][E_];
    __shared__ float s_sc[A_];
    __shared__ float s_c1[E_];
    __shared__ float s_c2[A_][E_];

    float sum2 = 0.f, sumb = 0.f;
#pragma unroll
    for (int j = 0; j < 3; j++) {
        sum2 += r2_w[tid + j * 256];
        sumb += r2_b[tid + j * 256];
    }
    red[tid] = sum2; __syncthreads();
    for (int st = 128; st > 0; st >>= 1) { if (tid < st) red[tid] += red[tid + st]; __syncthreads(); }
    if (tid == 0) s_mr2 = red[0] * (1.f / C_);
    __syncthreads();
    red[tid] = sumb; __syncthreads();
    for (int st = 128; st > 0; st >>= 1) { if (tid < st) red[tid] += red[tid + st]; __syncthreads(); }
    if (tid == 0) s_mrb = red[0] * (1.f / C_);
    __syncthreads();

    if (tid < A_) {
        int a = tid;
        float g[E_];
#pragma unroll
        for (int e = 0; e < E_; e++)
            g[e] = gate[b * E_ + e] + gate[(B_ + a) * E_ + e] + gate_b[e];
        int mi = 0;
#pragma unroll
        for (int e = 1; e < E_; e++) if (g[e] < g[mi]) mi = e;
        float mx = -INFINITY;
#pragma unroll
        for (int e = 0; e < E_; e++) if (e != mi && g[e] > mx) mx = g[e];
        float ssum = 0.f, we[E_];
#pragma unroll
        for (int e = 0; e < E_; e++) {
            we[e] = (e == mi) ? 0.f : __expf(g[e] - mx);
            ssum += we[e];
        }
        float inv = 1.f / ssum;
#pragma unroll
        for (int e = 0; e < E_; e++) s_w[a][e] = we[e] * inv;
        float xv = dr[b] + dr[B_ + a] + r1_b[0];
        float hg = 0.5f * xv * (1.f + tanhf(0.7978845608028654f * (xv + 0.044715f * xv * xv * xv)));
        s_sc[a] = hg * s_mr2 + s_mrb;
    }
    __syncthreads();

    if (tid == 0) {
        bool excl[A_];
        for (int a = 0; a < A_; a++) excl[a] = false;
        for (int r = 0; r < 3; r++) {
            int mi = -1; float mv = INFINITY;
            for (int a = 0; a < A_; a++)
                if (!excl[a] && s_sc[a] < mv) { mv = s_sc[a]; mi = a; }
            excl[mi] = true;
        }
        float smax = -INFINITY;
        for (int a = 0; a < A_; a++) if (!excl[a] && s_sc[a] > smax) smax = s_sc[a];
        float ssum = 0.f, wt[A_];
        for (int a = 0; a < A_; a++) {
            wt[a] = excl[a] ? 0.f : __expf(s_sc[a] - smax);
            ssum += wt[a];
        }
        float inv = 1.f / ssum;
        for (int e = 0; e < E_; e++) {
            float c1 = 0.f;
            for (int a = 0; a < A_; a++) {
                float c2 = wt[a] * inv * s_w[a][e];
                s_c2[a][e] = c2;
                c1 += c2;
            }
            s_c1[e] = c1;
        }
    }
    __syncthreads();

#pragma unroll
    for (int j = 0; j < 3; j++) {
        int c = tid + j * 256;
        float v = 0.f;
#pragma unroll
        for (int e = 0; e < E_; e++)
            v += s_c1[e] * (Yw[(size_t)b * (E_ * C_) + e * C_ + c] + exp_b[e * C_ + c]);
#pragma unroll
        for (int a = 0; a < A_; a++)
#pragma unroll
            for (int e = 0; e < E_; e++)
                v += s_c2[a][e] * Yw[(size_t)(B_ + a) * (E_ * C_) + e * C_ + c];
        out[(size_t)b * C_ + c] = v;
    }
}

// ---------------- launcher -------------------------------------------------
extern "C" void kernel_launch(void* const* d_in, const int* in_sizes, int n_in,
                              void* d_out, int out_size)
{
    (void)in_sizes; (void)n_in; (void)out_size;
    const float* text   = (const float*)d_in[0];
    const float* vcls   = (const float*)d_in[1];
    const float* x      = (const float*)d_in[2];
    const float* prompt = (const float*)d_in[3];
    const float* Wq = (const float*)d_in[4];
    const float* bq = (const float*)d_in[5];
    const float* Wk = (const float*)d_in[6];
    // d_in[7] = bk : per-(b,h) constant logit shift -> softmax-invariant, unused
    const float* Wv = (const float*)d_in[8];
    const float* bv = (const float*)d_in[9];
    const float* Wo = (const float*)d_in[10];
    const float* bo = (const float*)d_in[11];
    const float* gate_w = (const float*)d_in[12];
    const float* gate_b = (const float*)d_in[13];
    const float* exp_w  = (const float*)d_in[14];
    const float* exp_b  = (const float*)d_in[15];
    const float* r1_w   = (const float*)d_in[16];
    const float* r1_b   = (const float*)d_in[17];
    const float* r2_w   = (const float*)d_in[18];
    const float* r2_b   = (const float*)d_in[19];
    float* out = (float*)d_out;

    void* p;
    cudaGetSymbolAddress(&p, g_qb);    float* qb    = (float*)p;
    cudaGetSymbolAddress(&p, g_qhat);  float* qhat  = (float*)p;
    cudaGetSymbolAddress(&p, g_xbar);  float* xbar  = (float*)p;
    cudaGetSymbolAddress(&p, g_o);     float* o     = (float*)p;
    cudaGetSymbolAddress(&p, g_uP);    float* uP    = (float*)p;
    cudaGetSymbolAddress(&p, g_Yw);    float* Yw    = (float*)p;
    cudaGetSymbolAddress(&p, g_gate);  float* gate  = (float*)p;
    cudaGetSymbolAddress(&p, g_dr);    float* dr    = (float*)p;
    cudaGetSymbolAddress(&p, g_split); float* split = (float*)p;
    cudaGetSymbolAddress(&p, g_pacc);  float* pacc  = (float*)p;
    cudaGetSymbolAddress(&p, g_pms);   float2* pms  = (float2*)p;

    // prompt rows of uP (independent)
    copy_prompt_k<<<A_, C_>>>(prompt, uP);

    // qb = text @ Wq^T + bq   (split-K 4)
    gemm2_k<true, true, false, false><<<dim3(12, 4, 4), 256>>>(
        B_, C_, C_, 4, text, C_, 0, Wq, C_, 0, split, 0, 0,
        nullptr, 0, nullptr, 0);
    reduce_k<true, false><<<dim3(768, 1), 256>>>(
        B_, C_, 4, split, qb, C_, 0, bq, 0, nullptr, 0);

    // qhat[b,h,:] = Wk_h^T qb_h   (batched over h, K=96, direct)
    gemm2_k<false, false, false, false><<<dim3(12, 4, 8), 256>>>(
        B_, C_, D_, 1, qb, C_, D_, Wk, C_, D_ * C_, qhat, H_ * C_, C_,
        nullptr, 0, nullptr, 0);

    // attention partial pass (split-N 4, cp.async pipeline) + combine
    attn_part_k<<<dim3(SPLITS_, B_), 256>>>(x, qhat, pacc, pms);
    attn_comb_k<<<B_, 256>>>(pacc, pms, xbar);

    // o[b, h*96+d] = Wv_h @ xbar[b,h] + bv_h   (batched over h, split-K 4)
    gemm2_k<true, true, false, false><<<dim3(2, 4, 32), 256>>>(
        B_, D_, C_, 4, xbar, H_ * C_, C_, Wv, C_, D_ * C_, split, 0, 0,
        nullptr, 0, nullptr, 0);
    reduce_k<true, false><<<dim3(96, 8), 256>>>(
        B_, D_, 4, split, o, C_, D_, bv, D_, nullptr, 0);

    // uP rows 0..255: u = o @ Wo^T + bo + visual_cls   (split-K 4)
    gemm2_k<true, true, false, false><<<dim3(12, 4, 4), 256>>>(
        B_, C_, C_, 4, o, C_, 0, Wo, C_, 0, split, 0, 0,
        nullptr, 0, nullptr, 0);
    reduce_k<true, true><<<dim3(768, 1), 256>>>(
        B_, C_, 4, split, uP, C_, 0, bo, 0, vcls, C_);

    // expert outputs: Yw[i, e*C+o] = uP[i] @ exp_w[e]^T  (split-K 2)
    gemm2_k<true, true, false, false><<<dim3(48, 5, 2), 256>>>(
        B_ + A_, E_ * C_, C_, 2, uP, C_, 0, exp_w, C_, 0, split, 0, 0,
        nullptr, 0, nullptr, 0);
    reduce_k<false, false><<<dim3(3192, 1), 256>>>(
        B_ + A_, E_ * C_, 2, split, Yw, E_ * C_, 0, nullptr, 0, nullptr, 0);

    // gate + router-fc1 dots
    dots_k<<<B_ + A_, 160>>>(uP, gate_w, r1_w, gate, dr);

    // scores, top-k, softmax weights, weighted expert combine
    finale_k<<<B_, 256>>>(Yw, gate, dr, gate_b, exp_b, r1_b, r2_w, r2_b, out);
}

// round 4
// speedup vs baseline: 2.5058x; 1.1020x over previous
#include <cuda_runtime.h>
#include <math.h>
#include <stdint.h>

// Problem constants
#define B_ 256
#define N_ 256
#define C_ 768
#define A_ 10
#define H_ 8
#define E_ 4
#define D_ 96
#define SCALE_ 0.10206207261596575f   // 96^-0.5
#define SPLITS_ 4                     // attention N-splits

// ---------------- device scratch (no allocations allowed) ----------------
__device__ float g_qb[B_*C_];
__device__ float g_qhat[B_*H_*C_];
__device__ float g_xbar[B_*H_*C_];
__device__ float g_o[B_*C_];
__device__ float g_uP[(B_+A_)*C_];
__device__ float g_Yw[(B_+A_)*E_*C_];
__device__ float g_gate[(B_+A_)*E_];
__device__ float g_dr[(B_+A_)];
__device__ float g_split[2*266*3072];          // split-K partials
__device__ float g_pacc[SPLITS_*B_*H_*C_];     // attention partial accumulators
__device__ float2 g_pms[SPLITS_*B_*H_];        // attention partial (max, sum)

// ---------------- cp.async helpers ---------------------------------------
__device__ __forceinline__ void cp_async16(void* smem_dst, const void* gmem_src) {
    uint32_t d = (uint32_t)__cvta_generic_to_shared(smem_dst);
    asm volatile("cp.async.cg.shared.global [%0], [%1], 16;\n" :: "r"(d), "l"(gmem_src));
}
#define CP_COMMIT() asm volatile("cp.async.commit_group;\n" ::: "memory")
#define CP_WAIT(n)  asm volatile("cp.async.wait_group %0;\n" :: "n"(n) : "memory")

// ---------------- tf32 helpers --------------------------------------------
__device__ __forceinline__ uint32_t f2tf(float f) {
    uint32_t r;
    asm("cvt.rna.tf32.f32 %0, %1;" : "=r"(r) : "f"(f));
    return r;
}
__device__ __forceinline__ void mma_tf32(float* c,
    uint32_t a0, uint32_t a1, uint32_t a2, uint32_t a3,
    uint32_t b0, uint32_t b1)
{
    asm volatile(
        "mma.sync.aligned.m16n8k8.row.col.f32.tf32.tf32.f32 "
        "{%0,%1,%2,%3}, {%4,%5,%6,%7}, {%8,%9}, {%0,%1,%2,%3};"
        : "+f"(c[0]), "+f"(c[1]), "+f"(c[2]), "+f"(c[3])
        : "r"(a0), "r"(a1), "r"(a2), "r"(a3), "r"(b0), "r"(b1));
}

// ---------------- tf32 tensor-core GEMM, BM=BN=64, BK=16, 128 threads -----
// TRANSB=true : W is [N,K] row-major (torch Linear weight)
// TRANSB=false: W is [K,N] row-major
// PARTIAL: write raw tile to P[z][M][N], z = batch*KS + ks (reduced later)
template<bool TRANSB, bool PARTIAL, bool HAS_BIAS, bool HAS_EXTRA>
__global__ void __launch_bounds__(128) gemm_tc_k(
    int M, int N, int K, int KS,
    const float* __restrict__ X, int lda, int sx,
    const float* __restrict__ W, int ldw, int sw,
    float* __restrict__ Y, int ldy, int sy,
    const float* __restrict__ bias, int sb,
    const float* __restrict__ extra, int lde)
{
    constexpr int BM = 64, BN = 64, BK = 16;
    int z = blockIdx.z;
    int batch = z / KS, ks = z - batch * KS;
    int Kloc = K / KS, kbase = ks * Kloc;
    X += (size_t)batch * sx;
    W += (size_t)batch * sw;

    __shared__ uint32_t As[BK][BM + 4];
    __shared__ uint32_t Bs[BK][BN + 4];

    int tid = threadIdx.x;
    int lane = tid & 31, warp = tid >> 5;
    int wm = warp >> 1, wn = warp & 1;       // warp grid 2x2, warp tile 32x32
    int qr = lane & 3, qc = lane >> 2;
    int m0 = blockIdx.y * BM, n0 = blockIdx.x * BN;

    float acc[2][4][4];
#pragma unroll
    for (int i = 0; i < 2; i++)
#pragma unroll
        for (int j = 0; j < 4; j++)
#pragma unroll
            for (int l = 0; l < 4; l++) acc[i][j][l] = 0.f;

    for (int kb = kbase; kb < kbase + Kloc; kb += BK) {
        // ---- A tile: 64 rows x 16 k, convert to tf32, store [k][m] ----
#pragma unroll
        for (int j = 0; j < 2; j++) {
            int idx = tid + j * 128;
            int mi = idx >> 2, kq = idx & 3;
            int mm = m0 + mi;
            float4 v = make_float4(0.f, 0.f, 0.f, 0.f);
            if (mm < M) v = *reinterpret_cast<const float4*>(&X[(size_t)mm * lda + kb + kq * 4]);
            As[kq * 4 + 0][mi] = f2tf(v.x);
            As[kq * 4 + 1][mi] = f2tf(v.y);
            As[kq * 4 + 2][mi] = f2tf(v.z);
            As[kq * 4 + 3][mi] = f2tf(v.w);
        }
        // ---- B tile ----
        if (TRANSB) {
#pragma unroll
            for (int j = 0; j < 2; j++) {
                int idx = tid + j * 128;
                int ni = idx >> 2, kq = idx & 3;
                int nn = n0 + ni;
                float4 v = make_float4(0.f, 0.f, 0.f, 0.f);
                if (nn < N) v = *reinterpret_cast<const float4*>(&W[(size_t)nn * ldw + kb + kq * 4]);
                Bs[kq * 4 + 0][ni] = f2tf(v.x);
                Bs[kq * 4 + 1][ni] = f2tf(v.y);
                Bs[kq * 4 + 2][ni] = f2tf(v.z);
                Bs[kq * 4 + 3][ni] = f2tf(v.w);
            }
        } else {
#pragma unroll
            for (int j = 0; j < 2; j++) {
                int idx = tid + j * 128;
                int kr = idx >> 4, nq = idx & 15;
                int nn = n0 + nq * 4;
                float4 v = make_float4(0.f, 0.f, 0.f, 0.f);
                if (nn < N) v = *reinterpret_cast<const float4*>(&W[(size_t)(kb + kr) * ldw + nn]);
                Bs[kr][nq * 4 + 0] = f2tf(v.x);
                Bs[kr][nq * 4 + 1] = f2tf(v.y);
                Bs[kr][nq * 4 + 2] = f2tf(v.z);
                Bs[kr][nq * 4 + 3] = f2tf(v.w);
            }
        }
        __syncthreads();

#pragma unroll
        for (int kk = 0; kk < BK; kk += 8) {
            uint32_t af[2][4];
#pragma unroll
            for (int mi2 = 0; mi2 < 2; mi2++) {
                int rb = wm * 32 + mi2 * 16 + qc;
                af[mi2][0] = As[kk + qr][rb];
                af[mi2][1] = As[kk + qr][rb + 8];
                af[mi2][2] = As[kk + qr + 4][rb];
                af[mi2][3] = As[kk + qr + 4][rb + 8];
            }
            uint32_t bf[4][2];
#pragma unroll
            for (int ni = 0; ni < 4; ni++) {
                int cb = wn * 32 + ni * 8 + qc;
                bf[ni][0] = Bs[kk + qr][cb];
                bf[ni][1] = Bs[kk + qr + 4][cb];
            }
#pragma unroll
            for (int mi2 = 0; mi2 < 2; mi2++)
#pragma unroll
                for (int ni = 0; ni < 4; ni++)
                    mma_tf32(acc[mi2][ni],
                             af[mi2][0], af[mi2][1], af[mi2][2], af[mi2][3],
                             bf[ni][0], bf[ni][1]);
        }
        __syncthreads();
    }

    // ---- epilogue ----
#pragma unroll
    for (int mi2 = 0; mi2 < 2; mi2++) {
#pragma unroll
        for (int ni = 0; ni < 4; ni++) {
            int r0 = m0 + wm * 32 + mi2 * 16 + qc;
            int c0 = n0 + wn * 32 + ni * 8 + 2 * qr;
#pragma unroll
            for (int half = 0; half < 2; half++) {
                int r = r0 + half * 8;
                if (r >= M) continue;
#pragma unroll
                for (int cc = 0; cc < 2; cc++) {
                    int c = c0 + cc;
                    if (c >= N) continue;
                    float v = acc[mi2][ni][half * 2 + cc];
                    if (PARTIAL) {
                        Y[(size_t)z * M * N + (size_t)r * N + c] = v;
                    } else {
                        if (HAS_BIAS)  v += bias[(size_t)batch * sb + c];
                        if (HAS_EXTRA) v += extra[(size_t)r * lde + c];
                        Y[(size_t)batch * sy + (size_t)r * ldy + c] = v;
                    }
                }
            }
        }
    }
}

// ---------------- split-K reduce ------------------------------------------
template<bool HAS_BIAS, bool HAS_EXTRA>
__global__ void __launch_bounds__(256) reduce_k(
    int M, int N, int KS,
    const float* __restrict__ part, float* __restrict__ Y, int ldy, int sy,
    const float* __restrict__ bias, int sb,
    const float* __restrict__ extra, int lde)
{
    int z2 = blockIdx.y;
    int idx = blockIdx.x * 256 + threadIdx.x;
    if (idx >= M * N) return;
    int m = idx / N, n = idx - m * N;
    const float* p = part + (size_t)z2 * KS * M * N;
    float v = 0.f;
    for (int k = 0; k < KS; k++)
        v += p[(size_t)k * M * N + (size_t)m * N + n];
    if (HAS_BIAS)  v += bias[z2 * sb + n];
    if (HAS_EXTRA) v += extra[(size_t)m * lde + n];
    Y[(size_t)z2 * sy + (size_t)m * ldy + n] = v;
}

// ---------------- attention: split-N partial pass (cp.async pipeline) -----
__global__ void __launch_bounds__(256) attn_part_k(
    const float* __restrict__ xg, const float* __restrict__ qhat,
    float* __restrict__ pacc, float2* __restrict__ pms)
{
    int s = blockIdx.x, b = blockIdx.y;
    int tid = threadIdx.x, w = tid >> 5, lane = tid & 31;
    __shared__ __align__(16) float qh[H_ * C_];
    __shared__ __align__(16) float xs[2][4][C_];

    const float* xb = xg + ((size_t)b * N_ + (size_t)s * 64) * C_;

    auto issue = [&](int t) {
        int buf = t & 1;
        const float* src0 = xb + (size_t)t * 4 * C_;
#pragma unroll
        for (int i = 0; i < 3; i++) {
            int idx = tid + i * 256;
            int r = idx / 192, c4 = idx - r * 192;
            cp_async16(&xs[buf][r][c4 * 4], src0 + (size_t)r * C_ + c4 * 4);
        }
        CP_COMMIT();
    };

    issue(0);
    {
        const float4* src = (const float4*)(qhat + (size_t)b * H_ * C_);
        float4* dst = (float4*)qh;
#pragma unroll
        for (int i = 0; i < 6; i++) dst[tid + i * 256] = src[tid + i * 256];
    }

    const float* qw = qh + w * C_;
    float m = -INFINITY, ssum = 0.f;
    float acc[24];
#pragma unroll
    for (int j = 0; j < 24; j++) acc[j] = 0.f;

    for (int t = 0; t < 16; t++) {
        if (t < 15) { issue(t + 1); CP_WAIT(1); }
        else        { CP_WAIT(0); }
        __syncthreads();
        const int buf = t & 1;
#pragma unroll
        for (int r = 0; r < 4; r++) {
            const float* xr = xs[buf][r];
            float part = 0.f;
#pragma unroll
            for (int j = 0; j < 24; j++)
                part = fmaf(qw[j * 32 + lane], xr[j * 32 + lane], part);
#pragma unroll
            for (int o = 16; o; o >>= 1)
                part += __shfl_xor_sync(0xffffffffu, part, o);
            float l = part * SCALE_;
            if (l > m) {
                float corr = __expf(m - l);
                ssum = ssum * corr + 1.f;
#pragma unroll
                for (int j = 0; j < 24; j++)
                    acc[j] = fmaf(acc[j], corr, xr[j * 32 + lane]);
                m = l;
            } else {
                float p = __expf(l - m);
                ssum += p;
#pragma unroll
                for (int j = 0; j < 24; j++)
                    acc[j] = fmaf(p, xr[j * 32 + lane], acc[j]);
            }
        }
        __syncthreads();
    }

    float* outp = pacc + ((size_t)(s * B_ + b) * H_ + w) * C_;
#pragma unroll
    for (int j = 0; j < 24; j++) outp[j * 32 + lane] = acc[j];
    if (lane == 0) pms[(size_t)(s * B_ + b) * H_ + w] = make_float2(m, ssum);
}

// ---------------- attention: combine partials -----------------------------
__global__ void __launch_bounds__(256) attn_comb_k(
    const float* __restrict__ pacc, const float2* __restrict__ pms,
    float* __restrict__ xbar)
{
    int b = blockIdx.x;
    int tid = threadIdx.x, w = tid >> 5, lane = tid & 31;
    float2 ms[SPLITS_];
    float wf[SPLITS_];
#pragma unroll
    for (int i = 0; i < SPLITS_; i++) ms[i] = pms[(size_t)(i * B_ + b) * H_ + w];
    float M = ms[0].x;
#pragma unroll
    for (int i = 1; i < SPLITS_; i++) M = fmaxf(M, ms[i].x);
    float S = 0.f;
#pragma unroll
    for (int i = 0; i < SPLITS_; i++) { wf[i] = __expf(ms[i].x - M); S += ms[i].y * wf[i]; }
    float inv = 1.f / S;
#pragma unroll
    for (int j = 0; j < 24; j++) {
        float v = 0.f;
#pragma unroll
        for (int i = 0; i < SPLITS_; i++)
            v += pacc[((size_t)(i * B_ + b) * H_ + w) * C_ + j * 32 + lane] * wf[i];
        xbar[((size_t)b * H_ + w) * C_ + j * 32 + lane] = v * inv;
    }
}

// ---------------- prompt rows into uP -------------------------------------
__global__ void copy_prompt_k(const float* __restrict__ prompt, float* __restrict__ uP)
{
    uP[(size_t)(B_ + blockIdx.x) * C_ + threadIdx.x] =
        prompt[(size_t)blockIdx.x * C_ + threadIdx.x];
}

// ---------------- gate + router-fc1 dots ----------------------------------
__global__ void __launch_bounds__(160) dots_k(
    const float* __restrict__ uP, const float* __restrict__ gate_w,
    const float* __restrict__ r1_w, float* __restrict__ gate_out,
    float* __restrict__ dr_out)
{
    int i = blockIdx.x;
    int w = threadIdx.x >> 5, lane = threadIdx.x & 31;
    const float* u = uP + (size_t)i * C_;
    const float* v = (w < 4) ? (gate_w + w * C_) : r1_w;
    float p = 0.f;
#pragma unroll
    for (int j = 0; j < 24; j++) p = fmaf(u[j * 32 + lane], v[j * 32 + lane], p);
#pragma unroll
    for (int o = 16; o; o >>= 1) p += __shfl_xor_sync(0xffffffffu, p, o);
    if (lane == 0) {
        if (w < 4) gate_out[i * E_ + w] = p;
        else       dr_out[i] = p;
    }
}

// ---------------- final combine per batch row -----------------------------
__global__ void __launch_bounds__(256) finale_k(
    const float* __restrict__ Yw, const float* __restrict__ gate,
    const float* __restrict__ dr, const float* __restrict__ gate_b,
    const float* __restrict__ exp_b, const float* __restrict__ r1_b,
    const float* __restrict__ r2_w, const float* __restrict__ r2_b,
    float* __restrict__ out)
{
    int b = blockIdx.x, tid = threadIdx.x;
    __shared__ float red[256];
    __shared__ float s_mr2, s_mrb;
    __shared__ float s_w[A_][E_];
    __shared__ float s_sc[A_];
    __shared__ float s_c1[E_];
    __shared__ float s_c2[A_][E_];

    float sum2 = 0.f, sumb = 0.f;
#pragma unroll
    for (int j = 0; j < 3; j++) {
        sum2 += r2_w[tid + j * 256];
        sumb += r2_b[tid + j * 256];
    }
    red[tid] = sum2; __syncthreads();
    for (int st = 128; st > 0; st >>= 1) { if (tid < st) red[tid] += red[tid + st]; __syncthreads(); }
    if (tid == 0) s_mr2 = red[0] * (1.f / C_);
    __syncthreads();
    red[tid] = sumb; __syncthreads();
    for (int st = 128; st > 0; st >>= 1) { if (tid < st) red[tid] += red[tid + st]; __syncthreads(); }
    if (tid == 0) s_mrb = red[0] * (1.f / C_);
    __syncthreads();

    if (tid < A_) {
        int a = tid;
        float g[E_];
#pragma unroll
        for (int e = 0; e < E_; e++)
            g[e] = gate[b * E_ + e] + gate[(B_ + a) * E_ + e] + gate_b[e];
        int mi = 0;
#pragma unroll
        for (int e = 1; e < E_; e++) if (g[e] < g[mi]) mi = e;
        float mx = -INFINITY;
#pragma unroll
        for (int e = 0; e < E_; e++) if (e != mi && g[e] > mx) mx = g[e];
        float ssum = 0.f, we[E_];
#pragma unroll
        for (int e = 0; e < E_; e++) {
            we[e] = (e == mi) ? 0.f : __expf(g[e] - mx);
            ssum += we[e];
        }
        float inv = 1.f / ssum;
#pragma unroll
        for (int e = 0; e < E_; e++) s_w[a][e] = we[e] * inv;
        float xv = dr[b] + dr[B_ + a] + r1_b[0];
        float hg = 0.5f * xv * (1.f + tanhf(0.7978845608028654f * (xv + 0.044715f * xv * xv * xv)));
        s_sc[a] = hg * s_mr2 + s_mrb;
    }
    __syncthreads();

    if (tid == 0) {
        bool excl[A_];
        for (int a = 0; a < A_; a++) excl[a] = false;
        for (int r = 0; r < 3; r++) {
            int mi = -1; float mv = INFINITY;
            for (int a = 0; a < A_; a++)
                if (!excl[a] && s_sc[a] < mv) { mv = s_sc[a]; mi = a; }
            excl[mi] = true;
        }
        float smax = -INFINITY;
        for (int a = 0; a < A_; a++) if (!excl[a] && s_sc[a] > smax) smax = s_sc[a];
        float ssum = 0.f, wt[A_];
        for (int a = 0; a < A_; a++) {
            wt[a] = excl[a] ? 0.f : __expf(s_sc[a] - smax);
            ssum += wt[a];
        }
        float inv = 1.f / ssum;
        for (int e = 0; e < E_; e++) {
            float c1 = 0.f;
            for (int a = 0; a < A_; a++) {
                float c2 = wt[a] * inv * s_w[a][e];
                s_c2[a][e] = c2;
                c1 += c2;
            }
            s_c1[e] = c1;
        }
    }
    __syncthreads();

#pragma unroll
    for (int j = 0; j < 3; j++) {
        int c = tid + j * 256;
        float v = 0.f;
#pragma unroll
        for (int e = 0; e < E_; e++)
            v += s_c1[e] * (Yw[(size_t)b * (E_ * C_) + e * C_ + c] + exp_b[e * C_ + c]);
#pragma unroll
        for (int a = 0; a < A_; a++)
#pragma unroll
            for (int e = 0; e < E_; e++)
                v += s_c2[a][e] * Yw[(size_t)(B_ + a) * (E_ * C_) + e * C_ + c];
        out[(size_t)b * C_ + c] = v;
    }
}

// ---------------- launcher -------------------------------------------------
extern "C" void kernel_launch(void* const* d_in, const int* in_sizes, int n_in,
                              void* d_out, int out_size)
{
    (void)in_sizes; (void)n_in; (void)out_size;
    const float* text   = (const float*)d_in[0];
    const float* vcls   = (const float*)d_in[1];
    const float* x      = (const float*)d_in[2];
    const float* prompt = (const float*)d_in[3];
    const float* Wq = (const float*)d_in[4];
    const float* bq = (const float*)d_in[5];
    const float* Wk = (const float*)d_in[6];
    // d_in[7] = bk : per-(b,h) constant logit shift -> softmax-invariant, unused
    const float* Wv = (const float*)d_in[8];
    const float* bv = (const float*)d_in[9];
    const float* Wo = (const float*)d_in[10];
    const float* bo = (const float*)d_in[11];
    const float* gate_w = (const float*)d_in[12];
    const float* gate_b = (const float*)d_in[13];
    const float* exp_w  = (const float*)d_in[14];
    const float* exp_b  = (const float*)d_in[15];
    const float* r1_w   = (const float*)d_in[16];
    const float* r1_b   = (const float*)d_in[17];
    const float* r2_w   = (const float*)d_in[18];
    const float* r2_b   = (const float*)d_in[19];
    float* out = (float*)d_out;

    void* p;
    cudaGetSymbolAddress(&p, g_qb);    float* qb    = (float*)p;
    cudaGetSymbolAddress(&p, g_qhat);  float* qhat  = (float*)p;
    cudaGetSymbolAddress(&p, g_xbar);  float* xbar  = (float*)p;
    cudaGetSymbolAddress(&p, g_o);     float* o     = (float*)p;
    cudaGetSymbolAddress(&p, g_uP);    float* uP    = (float*)p;
    cudaGetSymbolAddress(&p, g_Yw);    float* Yw    = (float*)p;
    cudaGetSymbolAddress(&p, g_gate);  float* gate  = (float*)p;
    cudaGetSymbolAddress(&p, g_dr);    float* dr    = (float*)p;
    cudaGetSymbolAddress(&p, g_split); float* split = (float*)p;
    cudaGetSymbolAddress(&p, g_pacc);  float* pacc  = (float*)p;
    cudaGetSymbolAddress(&p, g_pms);   float2* pms  = (float2*)p;

    // prompt rows of uP (independent)
    copy_prompt_k<<<A_, C_>>>(prompt, uP);

    // qb = text @ Wq^T + bq   (tf32, split-K 4)
    gemm_tc_k<true, true, false, false><<<dim3(12, 4, 4), 128>>>(
        B_, C_, C_, 4, text, C_, 0, Wq, C_, 0, split, 0, 0,
        nullptr, 0, nullptr, 0);
    reduce_k<true, false><<<dim3(768, 1), 256>>>(
        B_, C_, 4, split, qb, C_, 0, bq, 0, nullptr, 0);

    // qhat[b,h,:] = Wk_h^T qb_h   (tf32, batched over h, K=96)
    gemm_tc_k<false, false, false, false><<<dim3(12, 4, 8), 128>>>(
        B_, C_, D_, 1, qb, C_, D_, Wk, C_, D_ * C_, qhat, H_ * C_, C_,
        nullptr, 0, nullptr, 0);

    // attention partial pass (split-N 4, cp.async pipeline) + combine
    attn_part_k<<<dim3(SPLITS_, B_), 256>>>(x, qhat, pacc, pms);
    attn_comb_k<<<B_, 256>>>(pacc, pms, xbar);

    // o[b, h*96+d] = Wv_h @ xbar[b,h] + bv_h   (tf32, batched h, split-K 4)
    gemm_tc_k<true, true, false, false><<<dim3(2, 4, 32), 128>>>(
        B_, D_, C_, 4, xbar, H_ * C_, C_, Wv, C_, D_ * C_, split, 0, 0,
        nullptr, 0, nullptr, 0);
    reduce_k<true, false><<<dim3(96, 8), 256>>>(
        B_, D_, 4, split, o, C_, D_, bv, D_, nullptr, 0);

    // uP rows 0..255: u = o @ Wo^T + bo + visual_cls   (tf32, split-K 4)
    gemm_tc_k<true, true, false, false><<<dim3(12, 4, 4), 128>>>(
        B_, C_, C_, 4, o, C_, 0, Wo, C_, 0, split, 0, 0,
        nullptr, 0, nullptr, 0);
    reduce_k<true, true><<<dim3(768, 1), 256>>>(
        B_, C_, 4, split, uP, C_, 0, bo, 0, vcls, C_);

    // expert outputs: Yw[i, e*C+o] = uP[i] @ exp_w[e]^T  (tf32, direct)
    gemm_tc_k<true, false, false, false><<<dim3(48, 5, 1), 128>>>(
        B_ + A_, E_ * C_, C_, 1, uP, C_, 0, exp_w, C_, 0, Yw, E_ * C_, 0,
        nullptr, 0, nullptr, 0);

    // gate + router-fc1 dots (fp32)
    dots_k<<<B_ + A_, 160>>>(uP, gate_w, r1_w, gate, dr);

    // scores, top-k, softmax weights, weighted expert combine
    finale_k<<<B_, 256>>>(Yw, gate, dr, gate_b, exp_b, r1_b, r2_w, r2_b, out);
}